// round 1
// baseline (speedup 1.0000x reference)
#include <cuda_runtime.h>
#include <cstdint>

// idx = (x % 256) % 64 == x & 63 for x >= 0 (inputs are randint(0,100000)).
// Output: one-hot [B, 64] float32 = 256 MB — pure store-bandwidth bound.
// Mapping: 16 threads per row; each thread writes one float4 (16B).
// Consecutive threads -> consecutive 16B chunks -> fully coalesced STG.128,
// every 128B line fully written (no partial-sector RMW).

__global__ __launch_bounds__(256)
void BasisEncoder_25890062860681_kernel(const int* __restrict__ x,
                                        float4* __restrict__ out,
                                        int n_rows) {
    long long tid = (long long)blockIdx.x * blockDim.x + threadIdx.x;
    long long total = (long long)n_rows * 16;
    if (tid >= total) return;

    int row = (int)(tid >> 4);
    int c   = (int)(tid & 15);

    int xv  = x[row];                 // broadcast within 16-thread group (L1 hit)
    int idx = xv & 63;                // (x % 256) % 64 for x >= 0
    int base = c << 2;

    float4 v;
    v.x = (idx == base + 0) ? 1.0f : 0.0f;
    v.y = (idx == base + 1) ? 1.0f : 0.0f;
    v.z = (idx == base + 2) ? 1.0f : 0.0f;
    v.w = (idx == base + 3) ? 1.0f : 0.0f;

    out[tid] = v;
}

extern "C" void kernel_launch(void* const* d_in, const int* in_sizes, int n_in,
                              void* d_out, int out_size) {
    const int* x = (const int*)d_in[0];
    float4* out  = (float4*)d_out;
    int n_rows   = in_sizes[0];               // 1048576

    long long total_threads = (long long)n_rows * 16;   // one float4 per thread
    int block = 256;
    long long grid = (total_threads + block - 1) / block;

    BasisEncoder_25890062860681_kernel<<<(unsigned)grid, block>>>(x, out, n_rows);
}

// round 3
// speedup vs baseline: 1.3503x; 1.3503x over previous
#include <cuda_runtime.h>
#include <cstdint>

// idx = (x % 256) % 64 == x & 63 for x >= 0 (inputs randint [0,100000)).
// Output one-hot [B, 64] fp32 = 256 MB -> pure store-BW problem.
//
// R2 changes vs R1:
//  - 256-bit stores (st.global.v8.f32, sm_10x): 1 warp store instr = 1024B,
//    halving LSU issue cost vs STG.128.
//  - 8 threads per row (32B each), ILP=4 grid-stride: 4 independent
//    LDG+STG chains per thread -> latency hiding, 8x fewer CTAs.

#define ILP 4

__device__ __forceinline__ void stg256(float* p,
                                       float a0, float a1, float a2, float a3,
                                       float a4, float a5, float a6, float a7) {
    asm volatile(
        "st.global.v8.f32 [%0], {%1,%2,%3,%4,%5,%6,%7,%8};"
        :: "l"(p), "f"(a0), "f"(a1), "f"(a2), "f"(a3),
           "f"(a4), "f"(a5), "f"(a6), "f"(a7)
        : "memory");
}

__global__ __launch_bounds__(256)
void BasisEncoder_25890062860681_kernel(const int* __restrict__ x,
                                        float* __restrict__ out,
                                        long long n_chunks) {   // 32B chunks total
    long long tid    = (long long)blockIdx.x * blockDim.x + threadIdx.x;
    long long stride = (long long)gridDim.x * blockDim.x;

    #pragma unroll
    for (int i = 0; i < ILP; i++) {
        long long chunk = tid + (long long)i * stride;
        if (chunk < n_chunks) {
            int row  = (int)(chunk >> 3);       // 8 chunks (of 8 floats) per row
            int c    = (int)(chunk & 7);
            int idx  = x[row] & 63;             // (x % 256) % 64, x >= 0
            int base = c << 3;

            float v0 = (idx == base + 0) ? 1.0f : 0.0f;
            float v1 = (idx == base + 1) ? 1.0f : 0.0f;
            float v2 = (idx == base + 2) ? 1.0f : 0.0f;
            float v3 = (idx == base + 3) ? 1.0f : 0.0f;
            float v4 = (idx == base + 4) ? 1.0f : 0.0f;
            float v5 = (idx == base + 5) ? 1.0f : 0.0f;
            float v6 = (idx == base + 6) ? 1.0f : 0.0f;
            float v7 = (idx == base + 7) ? 1.0f : 0.0f;

            stg256(out + chunk * 8, v0, v1, v2, v3, v4, v5, v6, v7);
        }
    }
}

extern "C" void kernel_launch(void* const* d_in, const int* in_sizes, int n_in,
                              void* d_out, int out_size) {
    const int* x = (const int*)d_in[0];
    float* out   = (float*)d_out;
    long long n_rows   = in_sizes[0];          // 1048576
    long long n_chunks = n_rows * 8;           // 8M x 32B = 256MB

    int block = 256;
    long long threads = (n_chunks + ILP - 1) / ILP;
    long long grid = (threads + block - 1) / block;   // 8192 CTAs

    BasisEncoder_25890062860681_kernel<<<(unsigned)grid, block>>>(x, out, n_chunks);
}